// round 13
// baseline (speedup 1.0000x reference)
#include <cuda_runtime.h>
#include <cuda_fp16.h>
#include <math.h>
#include <cstdint>

#define TOKENS  2048
#define HIDDEN  2048
#define INTER   5632
#define NEXPERTS 8
#define TOPK    2
#define NSLOTS  (TOKENS * TOPK)
#define BK 64
#define NW (NEXPERTS * HIDDEN * INTER)   // 92,274,688 (w1/w3); w2 same count

// ---------------- scratch ----------------
__device__ int    g_counts[NEXPERTS];
__device__ int    g_slots[NEXPERTS * NSLOTS];
__device__ __half g_xh[(size_t)TOKENS * HIDDEN];
__device__ float  g_gate[(size_t)NSLOTS * INTER];
__device__ __half g_h[(size_t)NSLOTS * INTER];
__device__ float  g_y[(size_t)NSLOTS * HIDDEN];
__device__ __half g_w1h[(size_t)NW];
__device__ __half g_w3h[(size_t)NW];
__device__ __half g_w2h[(size_t)NW];

// ---------------- helpers ----------------
__device__ __forceinline__ uint32_t smem_u32(const void* p) {
    uint32_t a;
    asm("{ .reg .u64 t; cvta.to.shared.u64 t, %1; cvt.u32.u64 %0, t; }" : "=r"(a) : "l"(p));
    return a;
}
__device__ __forceinline__ void cp16(uint32_t dst, const void* src, int sz) {
    asm volatile("cp.async.cg.shared.global [%0], [%1], 16, %2;"
                 :: "r"(dst), "l"(src), "r"(sz) : "memory");
}
#define CP_COMMIT() asm volatile("cp.async.commit_group;" ::: "memory")
#define CP_WAIT0()  asm volatile("cp.async.wait_group 0;" ::: "memory")

__device__ __forceinline__ void ldsm4(uint32_t* r, uint32_t addr) {
    asm volatile("ldmatrix.sync.aligned.m8n8.x4.shared.b16 {%0,%1,%2,%3}, [%4];"
                 : "=r"(r[0]), "=r"(r[1]), "=r"(r[2]), "=r"(r[3]) : "r"(addr));
}
__device__ __forceinline__ void ldsm4t(uint32_t* r, uint32_t addr) {
    asm volatile("ldmatrix.sync.aligned.m8n8.x4.trans.shared.b16 {%0,%1,%2,%3}, [%4];"
                 : "=r"(r[0]), "=r"(r[1]), "=r"(r[2]), "=r"(r[3]) : "r"(addr));
}
__device__ __forceinline__ void mma16(float* d, const uint32_t* a,
                                      uint32_t b0, uint32_t b1) {
    asm volatile(
        "mma.sync.aligned.m16n8k16.row.col.f32.f16.f16.f32 "
        "{%0,%1,%2,%3},{%4,%5,%6,%7},{%8,%9},{%0,%1,%2,%3};"
        : "+f"(d[0]), "+f"(d[1]), "+f"(d[2]), "+f"(d[3])
        : "r"(a[0]), "r"(a[1]), "r"(a[2]), "r"(a[3]), "r"(b0), "r"(b1));
}
__device__ __forceinline__ uint32_t pack2(float a, float b) {
    __half2 h = __floats2half2_rn(a, b);
    return *(uint32_t*)&h;
}
__device__ __forceinline__ float silu(float g) { return g / (1.f + expf(-g)); }

// ---------------- small kernels ----------------
__global__ void zero_counts_kernel() {
    if (threadIdx.x < NEXPERTS) g_counts[threadIdx.x] = 0;
}
__global__ void route_kernel(const int* __restrict__ idx) {
    int s = blockIdx.x * blockDim.x + threadIdx.x;
    if (s >= NSLOTS) return;
    int e = idx[s];
    int pos = atomicAdd(&g_counts[e], 1);
    g_slots[e * NSLOTS + pos] = s;
}
__global__ void round_x_kernel(const float* __restrict__ x) {
    int i = blockIdx.x * blockDim.x + threadIdx.x;
    if (i >= TOKENS * HIDDEN / 8) return;
    float4 v0 = *(const float4*)(x + i * 8);
    float4 v1 = *(const float4*)(x + i * 8 + 4);
    uint4 o;
    o.x = pack2(v0.x, v0.y);
    o.y = pack2(v0.z, v0.w);
    o.z = pack2(v1.x, v1.y);
    o.w = pack2(v1.z, v1.w);
    *(uint4*)(g_xh + (size_t)i * 8) = o;
}
// streaming f32 -> fp16 weight conversion
__global__ void conv_kernel(const float4* __restrict__ src, uint2* __restrict__ dst) {
    int i = blockIdx.x * blockDim.x + threadIdx.x;
    if (i >= NW / 4) return;
    float4 v = src[i];
    uint2 o;
    o.x = pack2(v.x, v.y);
    o.y = pack2(v.z, v.w);
    dst[i] = o;
}

// ================= unified grouped GEMM (all-fp16 operands) =================
// CTA 128x128, BK=64. 4 warps (2x2), warp tile 64x64, 128 threads.
// smem: A[2]@0 (16KB each, 128B rows m-major) | B[2]@32768 (16KB each, 256B rows k-major)
// EPI: 0 = raw f32 store; 1 = h = fp16(silu(gate)*acc)
#define G_SMEM 66048
extern __shared__ char smem[];

template<int KD, int ND, int SH, int EPI>
__global__ __launch_bounds__(128, 2)
void gemm_fp16(const __half* __restrict__ Abase,
               const __half* __restrict__ Wh,
               const float* __restrict__ Gate,
               float* __restrict__ OutF,
               __half* __restrict__ OutH) {
    const int e = blockIdx.z;
    const int count = g_counts[e];
    const int row0 = blockIdx.x * 128;
    if (row0 >= count) return;
    const int colbase = blockIdx.y * 128;

    const int tid  = threadIdx.x;
    const int lane = tid & 31;
    const int wid  = tid >> 5;
    const int q = lane & 3, gid = lane >> 2;
    const int warpm = wid >> 1;
    const int warpn = wid & 1;

    int* rowsS = (int*)(smem + 65536);
    if (tid < 128) {
        int r = row0 + tid;
        rowsS[tid] = (r < count) ? g_slots[e * NSLOTS + r] : -1;
    }
    __syncthreads();

    const uint32_t sb = smem_u32(smem);
    const __half* Wp = Wh + (size_t)e * KD * ND + colbase;

    // ---- A ldmatrix addressing (m-major 128B rows, XOR-folded) ----
    uint32_t BRA[4], MHA[4];
    {
        int cl = lane >> 4;
        #pragma unroll
        for (int mt = 0; mt < 4; mt++) {
            int row = warpm * 64 + mt * 16 + ((lane >> 3) & 1) * 8 + (lane & 7);
            int m3 = row & 7;
            BRA[mt] = (uint32_t)(row * 128 + ((cl ^ (m3 & 1)) << 4));
            MHA[mt] = (uint32_t)(m3 >> 1);
        }
    }
    // ---- B trans-ldmatrix addressing (k-major 256B rows) ----
    // lane -> k = ks*16 + (lane&15); n-granule g = warpn*8 + un*2 + (lane>>4)
    uint32_t BRBT[4];
    {
        int kb = lane & 15;
        int gb = warpn * 8 + (lane >> 4);
        #pragma unroll
        for (int un = 0; un < 4; un++)
            BRBT[un] = (uint32_t)(kb * 256 + (((gb + 2 * un) ^ (kb & 7)) << 4));
    }

    // ---- A cp.async tasks: row = (tid>>3)+16p, granule ag (8 halves) ----
    const int ar0 = tid >> 3;
    const int ag  = tid & 7;
    const uint32_t dstA0 = (uint32_t)(ar0 * 128 + ((ag ^ (ar0 & 7)) << 4));
    int aslot[8];
    const __half* pAsrc[8];
    #pragma unroll
    for (int p = 0; p < 8; p++) {
        aslot[p] = rowsS[ar0 + p * 16];
        int arow = (aslot[p] >= 0) ? (aslot[p] >> SH) : 0;
        pAsrc[p] = Abase + (size_t)arow * KD + ag * 8;
    }
    // ---- B cp.async tasks: k-row = tid>>1, granules g = (tid&1)*8 + p ----
    const int bk  = tid >> 1;
    const int bg0 = (tid & 1) * 8;
    const uint32_t dstB0 = (uint32_t)(bk * 256);
    const int bk3 = bk & 7;

    float acc[4][8][4];
    #pragma unroll
    for (int i = 0; i < 4; i++)
        #pragma unroll
        for (int j = 0; j < 8; j++)
            #pragma unroll
            for (int k = 0; k < 4; k++) acc[i][j][k] = 0.f;

    // ---- prologue: chunk 0 (all async) ----
    #pragma unroll
    for (int p = 0; p < 8; p++)
        cp16(sb + dstA0 + p * 2048, pAsrc[p], aslot[p] >= 0 ? 16 : 0);
    #pragma unroll
    for (int p = 0; p < 8; p++) {
        int g = bg0 + p;
        cp16(sb + 32768 + dstB0 + ((g ^ bk3) << 4),
             Wp + (size_t)bk * ND + g * 8, 16);
    }
    CP_COMMIT();
    CP_WAIT0();
    __syncthreads();

    const int NCH = KD / BK;
    for (int i = 0; i < NCH; i++) {
        const int cur = i & 1, nxt = cur ^ 1;
        const bool more = (i + 1 < NCH);

        if (more) {
            const int k0n = (i + 1) * BK;
            #pragma unroll
            for (int p = 0; p < 8; p++)
                cp16(sb + nxt * 16384 + dstA0 + p * 2048,
                     pAsrc[p] + (size_t)k0n,
                     aslot[p] >= 0 ? 16 : 0);
            const __half* Wn = Wp + (size_t)(k0n + bk) * ND;
            #pragma unroll
            for (int p = 0; p < 8; p++) {
                int g = bg0 + p;
                cp16(sb + 32768 + nxt * 16384 + dstB0 + ((g ^ bk3) << 4),
                     Wn + g * 8, 16);
            }
            CP_COMMIT();
        }

        const uint32_t bufA = sb + cur * 16384;
        const uint32_t bufB = sb + 32768 + cur * 16384;

        #pragma unroll
        for (int ks = 0; ks < 4; ks++) {
            uint32_t a[4][4];
            #pragma unroll
            for (int mt = 0; mt < 4; mt++)
                ldsm4(a[mt], bufA + BRA[mt] + (((uint32_t)ks ^ MHA[mt]) << 5));
            #pragma unroll
            for (int un = 0; un < 4; un++) {
                uint32_t b[4];
                ldsm4t(b, bufB + (uint32_t)ks * 4096 + BRBT[un]);
                #pragma unroll
                for (int mt = 0; mt < 4; mt++) {
                    mma16(acc[mt][2 * un + 0], a[mt], b[0], b[1]);
                    mma16(acc[mt][2 * un + 1], a[mt], b[2], b[3]);
                }
            }
        }

        CP_WAIT0();
        __syncthreads();
    }

    // ---- epilogue ----
    #pragma unroll
    for (int mt = 0; mt < 4; mt++) {
        #pragma unroll
        for (int half = 0; half < 2; half++) {
            int row = warpm * 64 + mt * 16 + gid + half * 8;
            int slot = rowsS[row];
            if (slot < 0) continue;
            size_t obase = (size_t)slot * ND + colbase + warpn * 64 + 2 * q;
            #pragma unroll
            for (int nt = 0; nt < 8; nt++) {
                float c0 = acc[mt][nt][half * 2 + 0];
                float c1 = acc[mt][nt][half * 2 + 1];
                if (EPI == 1) {
                    float2 gv = *(const float2*)(Gate + obase + nt * 8);
                    uint32_t h2 = pack2(silu(gv.x) * c0, silu(gv.y) * c1);
                    *(uint32_t*)(OutH + obase + nt * 8) = h2;
                } else {
                    float2 o; o.x = c0; o.y = c1;
                    *(float2*)(OutF + obase + nt * 8) = o;
                }
            }
        }
    }
}

// ---------------- combine ----------------
__global__ void combine_kernel(const float* __restrict__ ew,
                               float* __restrict__ out) {
    int i = blockIdx.x * blockDim.x + threadIdx.x;
    const int n4 = TOKENS * HIDDEN / 4;
    if (i >= n4) return;
    int t  = i / (HIDDEN / 4);
    int c4 = (i % (HIDDEN / 4)) * 4;
    float w0 = ew[t * 2 + 0];
    float w1v = ew[t * 2 + 1];
    float4 y0 = *(const float4*)(g_y + (size_t)(2 * t + 0) * HIDDEN + c4);
    float4 y1 = *(const float4*)(g_y + (size_t)(2 * t + 1) * HIDDEN + c4);
    float4 o;
    o.x = w0 * y0.x + w1v * y1.x;
    o.y = w0 * y0.y + w1v * y1.y;
    o.z = w0 * y0.z + w1v * y1.z;
    o.w = w0 * y0.w + w1v * y1.w;
    *(float4*)(out + (size_t)t * HIDDEN + c4) = o;
}

// ---------------- launch ----------------
extern "C" void kernel_launch(void* const* d_in, const int* in_sizes, int n_in,
                              void* d_out, int out_size) {
    const float* x   = (const float*)d_in[0];
    const float* ew  = (const float*)d_in[1];
    const float* w1  = (const float*)d_in[2];
    const float* w2  = (const float*)d_in[3];
    const float* w3  = (const float*)d_in[4];
    const int*   idx = (const int*)d_in[5];
    float* out = (float*)d_out;

    __half *gxh, *gh, *w1h, *w2h, *w3h;
    float *gg, *gy;
    cudaGetSymbolAddress((void**)&gxh, g_xh);
    cudaGetSymbolAddress((void**)&gg,  g_gate);
    cudaGetSymbolAddress((void**)&gh,  g_h);
    cudaGetSymbolAddress((void**)&gy,  g_y);
    cudaGetSymbolAddress((void**)&w1h, g_w1h);
    cudaGetSymbolAddress((void**)&w2h, g_w2h);
    cudaGetSymbolAddress((void**)&w3h, g_w3h);

    auto kGate = gemm_fp16<HIDDEN, INTER, 1, 0>;
    auto kUp   = gemm_fp16<HIDDEN, INTER, 1, 1>;
    auto kDown = gemm_fp16<INTER, HIDDEN, 0, 0>;
    cudaFuncSetAttribute(kGate, cudaFuncAttributeMaxDynamicSharedMemorySize, G_SMEM);
    cudaFuncSetAttribute(kUp,   cudaFuncAttributeMaxDynamicSharedMemorySize, G_SMEM);
    cudaFuncSetAttribute(kDown, cudaFuncAttributeMaxDynamicSharedMemorySize, G_SMEM);

    static cudaStream_t s2 = nullptr;
    static cudaEvent_t evF = nullptr, evJ = nullptr;
    if (!s2) {
        cudaStreamCreateWithFlags(&s2, cudaStreamNonBlocking);
        cudaEventCreateWithFlags(&evF, cudaEventDisableTiming);
        cudaEventCreateWithFlags(&evJ, cudaEventDisableTiming);
    }

    const int convBlocks = (NW / 4 + 255) / 256;

    zero_counts_kernel<<<1, 32>>>();
    route_kernel<<<NSLOTS / 256, 256>>>(idx);
    round_x_kernel<<<(TOKENS * HIDDEN / 8 + 255) / 256, 256>>>(x);

    // w1 conversion on main stream (gate depends on it)
    conv_kernel<<<convBlocks, 256>>>((const float4*)w1, (uint2*)w1h);

    // fork: w3 + w2 conversion overlapped with the gate GEMM
    cudaEventRecord(evF, 0);
    cudaStreamWaitEvent(s2, evF, 0);
    conv_kernel<<<convBlocks, 256, 0, s2>>>((const float4*)w3, (uint2*)w3h);
    conv_kernel<<<convBlocks, 256, 0, s2>>>((const float4*)w2, (uint2*)w2h);
    cudaEventRecord(evJ, s2);

    dim3 g1(NSLOTS / 128, INTER / 128, NEXPERTS);
    kGate<<<g1, 128, G_SMEM>>>(gxh, w1h, nullptr, gg, nullptr);

    // join: up needs w3h (and down needs w2h)
    cudaStreamWaitEvent(0, evJ, 0);
    kUp<<<g1, 128, G_SMEM>>>(gxh, w3h, gg, nullptr, gh);

    dim3 g2(NSLOTS / 128, HIDDEN / 128, NEXPERTS);
    kDown<<<g2, 128, G_SMEM>>>(gh, w2h, nullptr, gy, nullptr);

    combine_kernel<<<(TOKENS * HIDDEN / 4 + 255) / 256, 256>>>(ew, out);
}

// round 15
// speedup vs baseline: 1.2828x; 1.2828x over previous
#include <cuda_runtime.h>
#include <cuda_fp16.h>
#include <math.h>
#include <cstdint>

#define TOKENS  2048
#define HIDDEN  2048
#define INTER   5632
#define NEXPERTS 8
#define TOPK    2
#define NSLOTS  (TOKENS * TOPK)
#define BK 64

// ---------------- scratch ----------------
__device__ int    g_counts[NEXPERTS];
__device__ int    g_slots[NEXPERTS * NSLOTS];
__device__ __half g_xh[(size_t)TOKENS * HIDDEN];    // fp16-rounded x
__device__ float  g_gate[(size_t)NSLOTS * INTER];   // raw f32 gate
__device__ __half g_h[(size_t)NSLOTS * INTER];      // fp16 silu(g)*u
__device__ float  g_y[(size_t)NSLOTS * HIDDEN];

// ---------------- helpers ----------------
__device__ __forceinline__ uint32_t smem_u32(const void* p) {
    uint32_t a;
    asm("{ .reg .u64 t; cvta.to.shared.u64 t, %1; cvt.u32.u64 %0, t; }" : "=r"(a) : "l"(p));
    return a;
}
__device__ __forceinline__ void cp16(uint32_t dst, const void* src, int sz) {
    asm volatile("cp.async.cg.shared.global [%0], [%1], 16, %2;"
                 :: "r"(dst), "l"(src), "r"(sz) : "memory");
}
#define CP_COMMIT() asm volatile("cp.async.commit_group;" ::: "memory")
#define CP_WAIT0()  asm volatile("cp.async.wait_group 0;" ::: "memory")

__device__ __forceinline__ void ldsm4(uint32_t* r, uint32_t addr) {
    asm volatile("ldmatrix.sync.aligned.m8n8.x4.shared.b16 {%0,%1,%2,%3}, [%4];"
                 : "=r"(r[0]), "=r"(r[1]), "=r"(r[2]), "=r"(r[3]) : "r"(addr));
}
__device__ __forceinline__ void mma16(float* d, const uint32_t* a,
                                      uint32_t b0, uint32_t b1) {
    asm volatile(
        "mma.sync.aligned.m16n8k16.row.col.f32.f16.f16.f32 "
        "{%0,%1,%2,%3},{%4,%5,%6,%7},{%8,%9},{%0,%1,%2,%3};"
        : "+f"(d[0]), "+f"(d[1]), "+f"(d[2]), "+f"(d[3])
        : "r"(a[0]), "r"(a[1]), "r"(a[2]), "r"(a[3]), "r"(b0), "r"(b1));
}
__device__ __forceinline__ uint32_t pack2(float a, float b) {
    __half2 h = __floats2half2_rn(a, b);
    return *(uint32_t*)&h;
}
__device__ __forceinline__ float silu(float g) { return g / (1.f + expf(-g)); }

// ---------------- small kernels ----------------
__global__ void zero_counts_kernel() {
    if (threadIdx.x < NEXPERTS) g_counts[threadIdx.x] = 0;
}
__global__ void route_kernel(const int* __restrict__ idx) {
    int s = blockIdx.x * blockDim.x + threadIdx.x;
    if (s >= NSLOTS) return;
    int e = idx[s];
    int pos = atomicAdd(&g_counts[e], 1);
    g_slots[e * NSLOTS + pos] = s;
}
__global__ void round_x_kernel(const float* __restrict__ x) {
    int i = blockIdx.x * blockDim.x + threadIdx.x;
    if (i >= TOKENS * HIDDEN / 8) return;
    float4 v0 = *(const float4*)(x + i * 8);
    float4 v1 = *(const float4*)(x + i * 8 + 4);
    uint4 o;
    o.x = pack2(v0.x, v0.y);
    o.y = pack2(v0.z, v0.w);
    o.z = pack2(v1.x, v1.y);
    o.w = pack2(v1.z, v1.w);
    *(uint4*)(g_xh + (size_t)i * 8) = o;
}

// ================= unified grouped GEMM (fp16 mma, smem-staged f32 B) =================
// CTA 128x128, BK=64. 4 warps (2x2), warp tile 64x64, 128 threads.
// smem: A[2]@0 (16KB each) | Bf16[2]@32768 (16KB each) | stageF32@65536 (32KB) | rows@98304
// EPI: 0 = raw f32 store; 1 = h = fp16(silu(gate)*acc)
#define OFF_BF16 32768
#define OFF_STG  65536
#define OFF_ROWS 98304
#define G_SMEM   98944
extern __shared__ char smem[];

template<int KD, int ND, int SH, int EPI>
__global__ __launch_bounds__(128, 2)
void gemm_fp16(const __half* __restrict__ Abase,
               const float* __restrict__ Wbase,
               const float* __restrict__ Gate,
               float* __restrict__ OutF,
               __half* __restrict__ OutH) {
    const int e = blockIdx.z;
    const int count = g_counts[e];
    const int row0 = blockIdx.x * 128;
    if (row0 >= count) return;
    const int colbase = blockIdx.y * 128;

    const int tid  = threadIdx.x;
    const int lane = tid & 31;
    const int wid  = tid >> 5;
    const int q = lane & 3, gid = lane >> 2;
    const int warpm = wid >> 1;
    const int warpn = wid & 1;

    int* rowsS = (int*)(smem + OFF_ROWS);
    if (tid < 128) {
        int r = row0 + tid;
        rowsS[tid] = (r < count) ? g_slots[e * NSLOTS + r] : -1;
    }
    __syncthreads();

    const uint32_t sb = smem_u32(smem);
    const float* Wp = Wbase + (size_t)e * KD * ND + colbase;

    // ---- ldmatrix address precompute (XOR-folded, 128B rows of 64 halves) ----
    uint32_t BRA[4], MHA[4];
    {
        int cl = lane >> 4;
        #pragma unroll
        for (int mt = 0; mt < 4; mt++) {
            int row = warpm * 64 + mt * 16 + ((lane >> 3) & 1) * 8 + (lane & 7);
            int m3 = row & 7;
            BRA[mt] = (uint32_t)(row * 128 + ((cl ^ (m3 & 1)) << 4));
            MHA[mt] = (uint32_t)(m3 >> 1);
        }
    }
    uint32_t BRB[4], MHB[4];
    {
        int cB = (lane >> 3) & 1;
        int jt = lane >> 4;
        #pragma unroll
        for (int u = 0; u < 4; u++) {
            int row = warpn * 64 + (2 * u + jt) * 8 + (lane & 7);
            int m3 = row & 7;
            BRB[u] = (uint32_t)(row * 128 + ((cB ^ (m3 & 1)) << 4));
            MHB[u] = (uint32_t)(m3 >> 1);
        }
    }

    // ---- A cp.async tasks ----
    const int ar0 = tid >> 3;
    const int ag  = tid & 7;
    const uint32_t dstA0 = (uint32_t)(ar0 * 128 + ((ag ^ (ar0 & 7)) << 4));
    int aslot[8];
    const __half* pAsrc[8];
    #pragma unroll
    for (int p = 0; p < 8; p++) {
        aslot[p] = rowsS[ar0 + p * 16];
        int arow = (aslot[p] >= 0) ? (aslot[p] >> SH) : 0;
        pAsrc[p] = Abase + (size_t)arow * KD + ag * 8;
    }
    // ---- B stage cp.async tasks: 16 tasks, k-row-major f32 staging (512B rows) ----
    // task p: lin = tid + 128p -> krow = lin>>5, nf4 = lin&31
    // dst = stage + krow*512 + nf4*16 ; src = Wp + (k0+krow)*ND + nf4*4

    float acc[4][8][4];
    #pragma unroll
    for (int i = 0; i < 4; i++)
        #pragma unroll
        for (int j = 0; j < 8; j++)
            #pragma unroll
            for (int k = 0; k < 4; k++) acc[i][j][k] = 0.f;

    // ---- convert helper: stage -> Bf16[buf]; thread t handles n-row t ----
    #define CONVERT_B(bufoff)                                                   \
        { char* bf = smem + (bufoff);                                           \
          _Pragma("unroll")                                                     \
          for (int g = 0; g < 8; g++) {                                         \
              float f0 = *(const float*)(smem + OFF_STG + (8*g+0)*512 + tid*4); \
              float f1 = *(const float*)(smem + OFF_STG + (8*g+1)*512 + tid*4); \
              float f2 = *(const float*)(smem + OFF_STG + (8*g+2)*512 + tid*4); \
              float f3 = *(const float*)(smem + OFF_STG + (8*g+3)*512 + tid*4); \
              float f4 = *(const float*)(smem + OFF_STG + (8*g+4)*512 + tid*4); \
              float f5 = *(const float*)(smem + OFF_STG + (8*g+5)*512 + tid*4); \
              float f6 = *(const float*)(smem + OFF_STG + (8*g+6)*512 + tid*4); \
              float f7 = *(const float*)(smem + OFF_STG + (8*g+7)*512 + tid*4); \
              uint4 o;                                                          \
              o.x = pack2(f0, f1); o.y = pack2(f2, f3);                         \
              o.z = pack2(f4, f5); o.w = pack2(f6, f7);                         \
              *(uint4*)(bf + tid * 128 + ((g ^ (tid & 7)) << 4)) = o;           \
          } }

    #define STAGE_B(k0)                                                         \
        { _Pragma("unroll")                                                     \
          for (int p = 0; p < 16; p++) {                                        \
              int lin = tid + 128 * p;                                          \
              int krow = lin >> 5, nf4 = lin & 31;                              \
              cp16(sb + OFF_STG + krow * 512 + nf4 * 16,                        \
                   Wp + (size_t)((k0) + krow) * ND + nf4 * 4, 16);              \
          } }

    // ---- prologue ----
    #pragma unroll
    for (int p = 0; p < 8; p++)
        cp16(sb + dstA0 + p * 2048, pAsrc[p], aslot[p] >= 0 ? 16 : 0);
    STAGE_B(0);
    CP_COMMIT();
    CP_WAIT0();
    __syncthreads();
    CONVERT_B(OFF_BF16);
    __syncthreads();

    const int NCH = KD / BK;
    for (int i = 0; i < NCH; i++) {
        const int cur = i & 1, nxt = cur ^ 1;
        const bool more = (i + 1 < NCH);

        if (more) {
            const int k0n = (i + 1) * BK;
            #pragma unroll
            for (int p = 0; p < 8; p++)
                cp16(sb + nxt * 16384 + dstA0 + p * 2048,
                     pAsrc[p] + (size_t)k0n,
                     aslot[p] >= 0 ? 16 : 0);
            STAGE_B(k0n);
            CP_COMMIT();
        }

        const uint32_t bufA = sb + cur * 16384;
        const uint32_t bufB = sb + OFF_BF16 + cur * 16384;

        #pragma unroll
        for (int ks = 0; ks < 4; ks++) {
            uint32_t a[4][4], b[4][4];
            #pragma unroll
            for (int mt = 0; mt < 4; mt++)
                ldsm4(a[mt], bufA + BRA[mt] + (((uint32_t)ks ^ MHA[mt]) << 5));
            #pragma unroll
            for (int u = 0; u < 4; u++)
                ldsm4(b[u], bufB + BRB[u] + (((uint32_t)ks ^ MHB[u]) << 5));
            #pragma unroll
            for (int mt = 0; mt < 4; mt++)
                #pragma unroll
                for (int nt = 0; nt < 8; nt++)
                    mma16(acc[mt][nt], a[mt],
                          b[nt >> 1][2 * (nt & 1)], b[nt >> 1][2 * (nt & 1) + 1]);
        }

        CP_WAIT0();
        __syncthreads();
        if (more) {
            CONVERT_B(OFF_BF16 + nxt * 16384);
            __syncthreads();
        }
    }
    #undef CONVERT_B
    #undef STAGE_B

    // ---- epilogue ----
    #pragma unroll
    for (int mt = 0; mt < 4; mt++) {
        #pragma unroll
        for (int half = 0; half < 2; half++) {
            int row = warpm * 64 + mt * 16 + gid + half * 8;
            int slot = rowsS[row];
            if (slot < 0) continue;
            size_t obase = (size_t)slot * ND + colbase + warpn * 64 + 2 * q;
            #pragma unroll
            for (int nt = 0; nt < 8; nt++) {
                float c0 = acc[mt][nt][half * 2 + 0];
                float c1 = acc[mt][nt][half * 2 + 1];
                if (EPI == 1) {
                    float2 gv = *(const float2*)(Gate + obase + nt * 8);
                    uint32_t h2 = pack2(silu(gv.x) * c0, silu(gv.y) * c1);
                    *(uint32_t*)(OutH + obase + nt * 8) = h2;
                } else {
                    float2 o; o.x = c0; o.y = c1;
                    *(float2*)(OutF + obase + nt * 8) = o;
                }
            }
        }
    }
}

// ---------------- combine ----------------
__global__ void combine_kernel(const float* __restrict__ ew,
                               float* __restrict__ out) {
    int i = blockIdx.x * blockDim.x + threadIdx.x;
    const int n4 = TOKENS * HIDDEN / 4;
    if (i >= n4) return;
    int t  = i / (HIDDEN / 4);
    int c4 = (i % (HIDDEN / 4)) * 4;
    float w0 = ew[t * 2 + 0];
    float w1v = ew[t * 2 + 1];
    float4 y0 = *(const float4*)(g_y + (size_t)(2 * t + 0) * HIDDEN + c4);
    float4 y1 = *(const float4*)(g_y + (size_t)(2 * t + 1) * HIDDEN + c4);
    float4 o;
    o.x = w0 * y0.x + w1v * y1.x;
    o.y = w0 * y0.y + w1v * y1.y;
    o.z = w0 * y0.z + w1v * y1.z;
    o.w = w0 * y0.w + w1v * y1.w;
    *(float4*)(out + (size_t)t * HIDDEN + c4) = o;
}

// ---------------- launch ----------------
extern "C" void kernel_launch(void* const* d_in, const int* in_sizes, int n_in,
                              void* d_out, int out_size) {
    const float* x   = (const float*)d_in[0];
    const float* ew  = (const float*)d_in[1];
    const float* w1  = (const float*)d_in[2];
    const float* w2  = (const float*)d_in[3];
    const float* w3  = (const float*)d_in[4];
    const int*   idx = (const int*)d_in[5];
    float* out = (float*)d_out;

    __half *gxh, *gh;
    float *gg, *gy;
    cudaGetSymbolAddress((void**)&gxh, g_xh);
    cudaGetSymbolAddress((void**)&gg,  g_gate);
    cudaGetSymbolAddress((void**)&gh,  g_h);
    cudaGetSymbolAddress((void**)&gy,  g_y);

    auto kGate = gemm_fp16<HIDDEN, INTER, 1, 0>;
    auto kUp   = gemm_fp16<HIDDEN, INTER, 1, 1>;
    auto kDown = gemm_fp16<INTER, HIDDEN, 0, 0>;
    cudaFuncSetAttribute(kGate, cudaFuncAttributeMaxDynamicSharedMemorySize, G_SMEM);
    cudaFuncSetAttribute(kUp,   cudaFuncAttributeMaxDynamicSharedMemorySize, G_SMEM);
    cudaFuncSetAttribute(kDown, cudaFuncAttributeMaxDynamicSharedMemorySize, G_SMEM);

    zero_counts_kernel<<<1, 32>>>();
    route_kernel<<<NSLOTS / 256, 256>>>(idx);
    round_x_kernel<<<(TOKENS * HIDDEN / 8 + 255) / 256, 256>>>(x);

    dim3 g1(NSLOTS / 128, INTER / 128, NEXPERTS);   // Mtile fastest for L2 reuse
    kGate<<<g1, 128, G_SMEM>>>(gxh, w1, nullptr, gg, nullptr);
    kUp  <<<g1, 128, G_SMEM>>>(gxh, w3, gg, nullptr, gh);

    dim3 g2(NSLOTS / 128, HIDDEN / 128, NEXPERTS);
    kDown<<<g2, 128, G_SMEM>>>(gh, w2, nullptr, gy, nullptr);

    combine_kernel<<<(TOKENS * HIDDEN / 4 + 255) / 256, 256>>>(ew, out);
}